// round 3
// baseline (speedup 1.0000x reference)
#include <cuda_runtime.h>
#include <math.h>

// Problem constants
#define NB   16     // batch
#define C_IN 1024   // input channels
#define DI   512    // inner channels
#define NSP  1024   // spatial positions (32*32)

// Scratch (device globals: allocation-free per harness rules)
__device__ float g_tpg[(size_t)NB * 3 * DI * NSP];   // theta|phi|g per batch, each [DI][NSP]
__device__ float g_attn[(size_t)NB * NSP * NSP];     // attention matrix per batch
__device__ float g_y[(size_t)NB * NSP * DI];         // y = attn @ g^T, [NSP][DI] row-major

// ---------------------------------------------------------------------------
// Generic strided SGEMM: C[m,n] = alpha * sum_k A(m,k)*B(k,n) + bias[m] (+resid)
//   A(m,k) at A[m*sa_m + k*sa_k], B(k,n) at B[k*sb_k + n*sb_n]
//   C row-major with row stride sc_m (n-stride == 1). Batched via blockIdx.z.
// Template flags select which dim of A/B is unit-stride (for float4 loads):
//   AK  = true  -> A contiguous in k (sa_k==1), else contiguous in m (sa_m==1)
//   BNC = true  -> B contiguous in n (sb_n==1), else contiguous in k (sb_k==1)
// Requires M,N multiples of 128 and K multiple of 16 (true for all calls here).
// ---------------------------------------------------------------------------
template<bool AK, bool BNC>
__global__ __launch_bounds__(256) void gemm_k(
    const float* __restrict__ A, long long sa_m, long long sa_k, long long sa_b,
    const float* __restrict__ B, long long sb_k, long long sb_n, long long sb_b,
    float* __restrict__ C, long long sc_m, long long sc_b,
    const float* __restrict__ bias,
    const float* __restrict__ resid, long long sr_b,
    int K, float alpha)
{
    constexpr int BM = 128, BN = 128, BK = 16, TM = 8, TN = 8;
    __shared__ __align__(16) float As[BK][BM];
    __shared__ __align__(16) float Bs[BK][BN];

    const int b = blockIdx.z;
    A += (long long)b * sa_b;
    B += (long long)b * sb_b;
    C += (long long)b * sc_b;
    if (resid) resid += (long long)b * sr_b;

    const int m0 = blockIdx.y * BM;
    const int n0 = blockIdx.x * BN;
    const int tid = threadIdx.x;
    const int tx = tid & 15;   // N direction (16 threads)
    const int ty = tid >> 4;   // M direction (16 threads)

    float acc[TM][TN];
#pragma unroll
    for (int i = 0; i < TM; i++)
#pragma unroll
        for (int j = 0; j < TN; j++) acc[i][j] = 0.f;

    for (int k0 = 0; k0 < K; k0 += BK) {
        // ---- load A tile into As[k][m] ----
        if (AK) {
            // A contiguous in k: float4 along k, transpose into shared
#pragma unroll
            for (int it = 0; it < 2; ++it) {
                int idx = tid + it * 256;          // 0..511 over BM*BK/4
                int m   = idx >> 2;                // / (BK/4)
                int k4  = idx & 3;
                float4 v = *reinterpret_cast<const float4*>(
                    A + (long long)(m0 + m) * sa_m + (k0 + k4 * 4));
                As[k4 * 4 + 0][m] = v.x;
                As[k4 * 4 + 1][m] = v.y;
                As[k4 * 4 + 2][m] = v.z;
                As[k4 * 4 + 3][m] = v.w;
            }
        } else {
            // A contiguous in m: float4 along m, direct store
#pragma unroll
            for (int it = 0; it < 2; ++it) {
                int idx = tid + it * 256;
                int k   = idx >> 5;                // / (BM/4)
                int m4  = idx & 31;
                float4 v = *reinterpret_cast<const float4*>(
                    A + (long long)(k0 + k) * sa_k + (m0 + m4 * 4));
                *reinterpret_cast<float4*>(&As[k][m4 * 4]) = v;
            }
        }
        // ---- load B tile into Bs[k][n] ----
        if (BNC) {
#pragma unroll
            for (int it = 0; it < 2; ++it) {
                int idx = tid + it * 256;
                int k   = idx >> 5;
                int n4  = idx & 31;
                float4 v = *reinterpret_cast<const float4*>(
                    B + (long long)(k0 + k) * sb_k + (n0 + n4 * 4));
                *reinterpret_cast<float4*>(&Bs[k][n4 * 4]) = v;
            }
        } else {
            // B contiguous in k: float4 along k, transpose into shared
#pragma unroll
            for (int it = 0; it < 2; ++it) {
                int idx = tid + it * 256;
                int n   = idx >> 2;
                int k4  = idx & 3;
                float4 v = *reinterpret_cast<const float4*>(
                    B + (long long)(n0 + n) * sb_n + (k0 + k4 * 4));
                Bs[k4 * 4 + 0][n] = v.x;
                Bs[k4 * 4 + 1][n] = v.y;
                Bs[k4 * 4 + 2][n] = v.z;
                Bs[k4 * 4 + 3][n] = v.w;
            }
        }
        __syncthreads();

        // ---- compute ----
#pragma unroll
        for (int kk = 0; kk < BK; kk++) {
            float af[TM], bf[TN];
            *reinterpret_cast<float4*>(af)     = *reinterpret_cast<const float4*>(&As[kk][ty * TM]);
            *reinterpret_cast<float4*>(af + 4) = *reinterpret_cast<const float4*>(&As[kk][ty * TM + 4]);
            *reinterpret_cast<float4*>(bf)     = *reinterpret_cast<const float4*>(&Bs[kk][tx * TN]);
            *reinterpret_cast<float4*>(bf + 4) = *reinterpret_cast<const float4*>(&Bs[kk][tx * TN + 4]);
#pragma unroll
            for (int i = 0; i < TM; i++)
#pragma unroll
                for (int j = 0; j < TN; j++)
                    acc[i][j] = fmaf(af[i], bf[j], acc[i][j]);
        }
        __syncthreads();
    }

    // ---- epilogue ----
#pragma unroll
    for (int i = 0; i < TM; i++) {
        int m = m0 + ty * TM + i;
        float bv = bias ? bias[m] : 0.f;
        long long rowoff = (long long)m * sc_m + n0 + tx * TN;
#pragma unroll
        for (int j = 0; j < TN; j += 4) {
            float4 r;
            r.x = fmaf(alpha, acc[i][j + 0], bv);
            r.y = fmaf(alpha, acc[i][j + 1], bv);
            r.z = fmaf(alpha, acc[i][j + 2], bv);
            r.w = fmaf(alpha, acc[i][j + 3], bv);
            if (resid) {
                float4 xv = *reinterpret_cast<const float4*>(resid + rowoff + j);
                r.x += xv.x; r.y += xv.y; r.z += xv.z; r.w += xv.w;
            }
            *reinterpret_cast<float4*>(C + rowoff + j) = r;
        }
    }
}

// ---------------------------------------------------------------------------
// Row softmax over attn rows of length NSP=1024. One 256-thread block per row,
// 4 elements (one float4) per thread.
// ---------------------------------------------------------------------------
__global__ __launch_bounds__(256) void softmax_rows(float* __restrict__ attn)
{
    const long long row = blockIdx.x;
    float* p = attn + row * NSP;
    const int tid = threadIdx.x;
    __shared__ float red[8];

    float4 v = reinterpret_cast<float4*>(p)[tid];

    // max
    float mx = fmaxf(fmaxf(v.x, v.y), fmaxf(v.z, v.w));
#pragma unroll
    for (int o = 16; o > 0; o >>= 1)
        mx = fmaxf(mx, __shfl_xor_sync(0xffffffffu, mx, o));
    if ((tid & 31) == 0) red[tid >> 5] = mx;
    __syncthreads();
    float m_all = red[0];
#pragma unroll
    for (int w = 1; w < 8; w++) m_all = fmaxf(m_all, red[w]);
    __syncthreads();

    // exp + sum
    v.x = expf(v.x - m_all);
    v.y = expf(v.y - m_all);
    v.z = expf(v.z - m_all);
    v.w = expf(v.w - m_all);
    float s = v.x + v.y + v.z + v.w;
#pragma unroll
    for (int o = 16; o > 0; o >>= 1)
        s += __shfl_xor_sync(0xffffffffu, s, o);
    if ((tid & 31) == 0) red[tid >> 5] = s;
    __syncthreads();
    float s_all = 0.f;
#pragma unroll
    for (int w = 0; w < 8; w++) s_all += red[w];

    float inv = 1.f / s_all;
    v.x *= inv; v.y *= inv; v.z *= inv; v.w *= inv;
    reinterpret_cast<float4*>(p)[tid] = v;
}

// ---------------------------------------------------------------------------
// kernel_launch
// Inputs (metadata order): x, w_theta, b_theta, w_phi, b_phi, w_g, b_g, w_out, b_out
// ---------------------------------------------------------------------------
extern "C" void kernel_launch(void* const* d_in, const int* in_sizes, int n_in,
                              void* d_out, int out_size)
{
    (void)in_sizes; (void)n_in; (void)out_size;
    const float* x   = (const float*)d_in[0];
    const float* w_t = (const float*)d_in[1];
    const float* b_t = (const float*)d_in[2];
    const float* w_p = (const float*)d_in[3];
    const float* b_p = (const float*)d_in[4];
    const float* w_g = (const float*)d_in[5];
    const float* b_g = (const float*)d_in[6];
    const float* w_o = (const float*)d_in[7];
    const float* b_o = (const float*)d_in[8];
    float* out = (float*)d_out;

    float *tpg = nullptr, *attn = nullptr, *y = nullptr;
    cudaGetSymbolAddress((void**)&tpg,  g_tpg);
    cudaGetSymbolAddress((void**)&attn, g_attn);
    cudaGetSymbolAddress((void**)&y,    g_y);

    const long long SB_X = (long long)C_IN * NSP;   // per-batch x/out stride
    const long long SB_T = (long long)3 * DI * NSP; // per-batch tpg stride
    const long long SB_A = (long long)NSP * NSP;    // per-batch attn stride
    const long long SB_Y = (long long)NSP * DI;     // per-batch y stride
    dim3 blk(256);

    // --- projections: [DI x NSP] = W[DI x C_IN] @ x_b[C_IN x NSP] (+bias) ---
    gemm_k<true, true><<<dim3(NSP / 128, DI / 128, NB), blk>>>(
        w_t, C_IN, 1, 0,
        x,   NSP,  1, SB_X,
        tpg, NSP,  SB_T,
        b_t, nullptr, 0, C_IN, 1.f);
    gemm_k<true, true><<<dim3(NSP / 128, DI / 128, NB), blk>>>(
        w_p, C_IN, 1, 0,
        x,   NSP,  1, SB_X,
        tpg + (long long)DI * NSP, NSP, SB_T,
        b_p, nullptr, 0, C_IN, 1.f);
    gemm_k<true, true><<<dim3(NSP / 128, DI / 128, NB), blk>>>(
        w_g, C_IN, 1, 0,
        x,   NSP,  1, SB_X,
        tpg + (long long)2 * DI * NSP, NSP, SB_T,
        b_g, nullptr, 0, C_IN, 1.f);

    // --- scores: attn[i,j] = (1/sqrt(DI)) * sum_d theta[d,i] * phi[d,j] ---
    // A(m=i, k=d) = theta[d*NSP + i]  (m-contiguous)
    // B(k=d, n=j) = phi[d*NSP + j]    (n-contiguous)
    gemm_k<false, true><<<dim3(NSP / 128, NSP / 128, NB), blk>>>(
        tpg, 1, NSP, SB_T,
        tpg + (long long)DI * NSP, NSP, 1, SB_T,
        attn, NSP, SB_A,
        nullptr, nullptr, 0, DI, 1.0f / sqrtf((float)DI));

    // --- softmax over each attn row ---
    softmax_rows<<<NB * NSP, 256>>>(attn);

    // --- y[i,d] = sum_j attn[i,j] * g[d,j] ---
    // A(m=i, k=j) = attn row-major (k-contiguous)
    // B(k=j, n=d) = g[d*NSP + j]   (k-contiguous)
    gemm_k<true, false><<<dim3(DI / 128, NSP / 128, NB), blk>>>(
        attn, NSP, 1, SB_A,
        tpg + (long long)2 * DI * NSP, 1, NSP, SB_T,
        y, DI, SB_Y,
        nullptr, nullptr, 0, NSP, 1.f);

    // --- out[c,p] = x[c,p] + b_out[c] + sum_d w_out[c,d] * y[p,d] ---
    // A(m=c, k=d) = w_out row-major (k-contiguous)
    // B(k=d, n=p) = y[p*DI + d]     (k-contiguous)
    gemm_k<true, false><<<dim3(NSP / 128, C_IN / 128, NB), blk>>>(
        w_o, DI, 1, 0,
        y, 1, DI, SB_Y,
        out, NSP, SB_X,
        b_o, x, SB_X, DI, 1.f);
}